// round 1
// baseline (speedup 1.0000x reference)
#include <cuda_runtime.h>

#define T_TOK 8192
#define DIM 1024
#define NEXP 16
#define TOPK 2
#define INTER 2048
#define ATOT (T_TOK * TOPK)

#define BM 128
#define BN 64
#define BN2 128
#define BK 16
#define KPAD (BK + 4)

// ---------------- scratch (static device globals; no allocation) ----------------
__device__ float g_H[(size_t)ATOT * INTER];   // 134 MB intermediate H
__device__ int   g_ti[ATOT];
__device__ float g_tw[ATOT];
__device__ int   g_counts[NEXP];
__device__ int   g_offsets[NEXP];
__device__ int   g_cursor[NEXP];
__device__ int   g_tok[ATOT];
__device__ float g_w[ATOT];

// ---------------- helpers ----------------
__device__ __forceinline__ unsigned f2t(float f) {
    unsigned u;
    asm("cvt.rna.tf32.f32 %0, %1;" : "=r"(u) : "f"(f));
    return u;
}

__device__ __forceinline__ void mma8(float* c, unsigned a0, unsigned a1, unsigned a2, unsigned a3,
                                     unsigned b0, unsigned b1) {
    asm volatile(
        "mma.sync.aligned.m16n8k8.row.col.f32.tf32.tf32.f32 "
        "{%0,%1,%2,%3},{%4,%5,%6,%7},{%8,%9},{%0,%1,%2,%3};"
        : "+f"(c[0]), "+f"(c[1]), "+f"(c[2]), "+f"(c[3])
        : "r"(a0), "r"(a1), "r"(a2), "r"(a3), "r"(b0), "r"(b1));
}

__device__ __forceinline__ float silu_f(float v) {
    return v * (1.f / (1.f + __expf(-v)));
}

// ---------------- kernel 0: zero output + counters ----------------
__global__ void k_zero(float* __restrict__ y) {
    int i = blockIdx.x * blockDim.x + threadIdx.x;
    const int n4 = T_TOK * DIM / 4;
    if (i < n4) reinterpret_cast<float4*>(y)[i] = make_float4(0.f, 0.f, 0.f, 0.f);
    if (i < NEXP) { g_counts[i] = 0; g_cursor[i] = 0; }
}

// ---------------- kernel 1: gate (warp per token, fp32 exact) ----------------
__global__ __launch_bounds__(256) void k_gate(const float* __restrict__ x,
                                              const float* __restrict__ Wg,
                                              const float* __restrict__ bg) {
    const int warp = threadIdx.x >> 5, lane = threadIdx.x & 31;
    const int t = blockIdx.x * 8 + warp;
    if (t >= T_TOK) return;

    float acc[NEXP];
#pragma unroll
    for (int e = 0; e < NEXP; e++) acc[e] = 0.f;

    const float* xr = x + (size_t)t * DIM;
#pragma unroll 4
    for (int i = 0; i < DIM / 32; i++) {
        const int d = i * 32 + lane;
        const float xv = xr[d];
        const float4* wr = reinterpret_cast<const float4*>(Wg + (size_t)d * NEXP);
        float4 w0 = wr[0], w1 = wr[1], w2 = wr[2], w3 = wr[3];
        acc[0] += xv * w0.x;  acc[1] += xv * w0.y;  acc[2] += xv * w0.z;  acc[3] += xv * w0.w;
        acc[4] += xv * w1.x;  acc[5] += xv * w1.y;  acc[6] += xv * w1.z;  acc[7] += xv * w1.w;
        acc[8] += xv * w2.x;  acc[9] += xv * w2.y;  acc[10] += xv * w2.z; acc[11] += xv * w2.w;
        acc[12] += xv * w3.x; acc[13] += xv * w3.y; acc[14] += xv * w3.z; acc[15] += xv * w3.w;
    }
#pragma unroll
    for (int e = 0; e < NEXP; e++) {
        float v = acc[e];
#pragma unroll
        for (int o = 16; o > 0; o >>= 1) v += __shfl_xor_sync(0xffffffffu, v, o);
        acc[e] = v + bg[e];
    }
    // softmax numerator (shared denominator cancels in top-2 renormalization)
    float mx = acc[0];
#pragma unroll
    for (int e = 1; e < NEXP; e++) mx = fmaxf(mx, acc[e]);
    float p[NEXP];
#pragma unroll
    for (int e = 0; e < NEXP; e++) p[e] = __expf(acc[e] - mx);

    int i0, i1; float p0, p1;
    if (p[0] >= p[1]) { i0 = 0; p0 = p[0]; i1 = 1; p1 = p[1]; }
    else              { i0 = 1; p0 = p[1]; i1 = 0; p1 = p[0]; }
#pragma unroll
    for (int e = 2; e < NEXP; e++) {
        if (p[e] > p0)      { i1 = i0; p1 = p0; i0 = e; p0 = p[e]; }
        else if (p[e] > p1) { i1 = e; p1 = p[e]; }
    }
    if (lane == 0) {
        const float ws = p0 + p1;
        g_ti[2 * t] = i0;     g_tw[2 * t] = p0 / ws;
        g_ti[2 * t + 1] = i1; g_tw[2 * t + 1] = p1 / ws;
        atomicAdd(&g_counts[i0], 1);
        atomicAdd(&g_counts[i1], 1);
    }
}

// ---------------- kernel 2: prefix sum over 16 experts ----------------
__global__ void k_prefix() {
    int s = 0;
    for (int e = 0; e < NEXP; e++) { g_offsets[e] = s; s += g_counts[e]; }
}

// ---------------- kernel 3: scatter tokens into expert segments ----------------
__global__ void k_scatter() {
    const int t = blockIdx.x * blockDim.x + threadIdx.x;
    if (t >= T_TOK) return;
#pragma unroll
    for (int k = 0; k < TOPK; k++) {
        const int e = g_ti[2 * t + k];
        const int slot = atomicAdd(&g_cursor[e], 1);
        const int pos = g_offsets[e] + slot;
        g_tok[pos] = t;
        g_w[pos] = g_tw[2 * t + k];
    }
}

// ---------------- STS helpers ----------------
__device__ __forceinline__ void sts_a(unsigned (*As)[KPAD], int rA, int cA, float4 ra0, float4 ra1) {
    unsigned* p = &As[rA][cA];
    p[0] = f2t(ra0.x); p[1] = f2t(ra0.y); p[2] = f2t(ra0.z); p[3] = f2t(ra0.w);
    p = &As[rA + 64][cA];
    p[0] = f2t(ra1.x); p[1] = f2t(ra1.y); p[2] = f2t(ra1.z); p[3] = f2t(ra1.w);
}

__device__ __forceinline__ void sts_bT(unsigned (*Bs)[KPAD], int nB, int kB, float4 rb) {
    Bs[nB + 0][kB] = f2t(rb.x);
    Bs[nB + 1][kB] = f2t(rb.y);
    Bs[nB + 2][kB] = f2t(rb.z);
    Bs[nB + 3][kB] = f2t(rb.w);
}

// ---------------- kernel 4: fused GLU GEMM  H = silu(xW1+b1)*(xW3+b3) ----------------
__global__ __launch_bounds__(256, 1) void k_glu(const float* __restrict__ x,
                                                const float* __restrict__ W1, const float* __restrict__ b1,
                                                const float* __restrict__ W3, const float* __restrict__ b3) {
    const int e = blockIdx.z;
    const int cnt = g_counts[e];
    const int mt = blockIdx.y;
    if (mt * BM >= cnt) return;
    const int nt = blockIdx.x;
    const int seg = g_offsets[e];
    const int tid = threadIdx.x;

    __shared__ unsigned As[2][BM][KPAD];
    __shared__ unsigned B1s[2][BN][KPAD];
    __shared__ unsigned B3s[2][BN][KPAD];

    const int rA = tid >> 2;
    const int cA = (tid & 3) * 4;
    const int r0 = mt * BM + rA;
    const int r1 = r0 + 64;
    const int tok0 = (r0 < cnt) ? g_tok[seg + r0] : 0;
    const int tok1 = (r1 < cnt) ? g_tok[seg + r1] : 0;
    const float* a0p = x + (size_t)tok0 * DIM + cA;
    const float* a1p = x + (size_t)tok1 * DIM + cA;

    const int nB = (tid & 15) * 4;
    const int kB = tid >> 4;
    const size_t wbase = (size_t)e * DIM * INTER + (size_t)kB * INTER + (size_t)nt * BN + nB;
    const float* b1p = W1 + wbase;
    const float* b3p = W3 + wbase;

    const int warp = tid >> 5, lane = tid & 31;
    const int wm = warp & 3, wn = warp >> 2;
    const int g = lane >> 2, tg = lane & 3;

    float acc1[2][4][4], acc3[2][4][4];
#pragma unroll
    for (int i = 0; i < 2; i++)
#pragma unroll
        for (int j = 0; j < 4; j++)
#pragma unroll
            for (int q = 0; q < 4; q++) { acc1[i][j][q] = 0.f; acc3[i][j][q] = 0.f; }

    float4 ra0, ra1, rb1, rb3;
    ra0 = *reinterpret_cast<const float4*>(a0p);
    ra1 = *reinterpret_cast<const float4*>(a1p);
    rb1 = *reinterpret_cast<const float4*>(b1p);
    rb3 = *reinterpret_cast<const float4*>(b3p);
    sts_a(As[0], rA, cA, ra0, ra1);
    sts_bT(B1s[0], nB, kB, rb1);
    sts_bT(B3s[0], nB, kB, rb3);
    __syncthreads();

    const int NKT = DIM / BK;  // 64
#pragma unroll 1
    for (int kt = 0; kt < NKT; kt++) {
        const int nxt = kt + 1;
        if (nxt < NKT) {
            ra0 = *reinterpret_cast<const float4*>(a0p + nxt * BK);
            ra1 = *reinterpret_cast<const float4*>(a1p + nxt * BK);
            rb1 = *reinterpret_cast<const float4*>(b1p + (size_t)nxt * BK * INTER);
            rb3 = *reinterpret_cast<const float4*>(b3p + (size_t)nxt * BK * INTER);
        }
        const int buf = kt & 1;
#pragma unroll
        for (int ks = 0; ks < 2; ks++) {
            unsigned af[2][4];
#pragma unroll
            for (int mi = 0; mi < 2; mi++) {
                const int mr = wm * 32 + mi * 16;
                af[mi][0] = As[buf][mr + g][ks * 8 + tg];
                af[mi][1] = As[buf][mr + g + 8][ks * 8 + tg];
                af[mi][2] = As[buf][mr + g][ks * 8 + tg + 4];
                af[mi][3] = As[buf][mr + g + 8][ks * 8 + tg + 4];
            }
            unsigned bf1[4][2], bf3[4][2];
#pragma unroll
            for (int ni = 0; ni < 4; ni++) {
                const int nc = wn * 32 + ni * 8 + g;
                bf1[ni][0] = B1s[buf][nc][ks * 8 + tg];
                bf1[ni][1] = B1s[buf][nc][ks * 8 + tg + 4];
                bf3[ni][0] = B3s[buf][nc][ks * 8 + tg];
                bf3[ni][1] = B3s[buf][nc][ks * 8 + tg + 4];
            }
#pragma unroll
            for (int mi = 0; mi < 2; mi++)
#pragma unroll
                for (int ni = 0; ni < 4; ni++) {
                    mma8(acc1[mi][ni], af[mi][0], af[mi][1], af[mi][2], af[mi][3], bf1[ni][0], bf1[ni][1]);
                    mma8(acc3[mi][ni], af[mi][0], af[mi][1], af[mi][2], af[mi][3], bf3[ni][0], bf3[ni][1]);
                }
        }
        if (nxt < NKT) {
            const int b2f = nxt & 1;
            sts_a(As[b2f], rA, cA, ra0, ra1);
            sts_bT(B1s[b2f], nB, kB, rb1);
            sts_bT(B3s[b2f], nB, kB, rb3);
        }
        __syncthreads();
    }

    // epilogue: h = silu(v1)*v3
#pragma unroll
    for (int mi = 0; mi < 2; mi++) {
        const int rloc0 = mt * BM + wm * 32 + mi * 16 + g;
        const int rloc1 = rloc0 + 8;
#pragma unroll
        for (int ni = 0; ni < 4; ni++) {
            const int col = nt * BN + wn * 32 + ni * 8 + 2 * tg;
            const float bb1x = b1[e * INTER + col], bb1y = b1[e * INTER + col + 1];
            const float bb3x = b3[e * INTER + col], bb3y = b3[e * INTER + col + 1];
            if (rloc0 < cnt) {
                const float h0 = silu_f(acc1[mi][ni][0] + bb1x) * (acc3[mi][ni][0] + bb3x);
                const float h1 = silu_f(acc1[mi][ni][1] + bb1y) * (acc3[mi][ni][1] + bb3y);
                *reinterpret_cast<float2*>(&g_H[(size_t)(seg + rloc0) * INTER + col]) = make_float2(h0, h1);
            }
            if (rloc1 < cnt) {
                const float h0 = silu_f(acc1[mi][ni][2] + bb1x) * (acc3[mi][ni][2] + bb3x);
                const float h1 = silu_f(acc1[mi][ni][3] + bb1y) * (acc3[mi][ni][3] + bb3y);
                *reinterpret_cast<float2*>(&g_H[(size_t)(seg + rloc1) * INTER + col]) = make_float2(h0, h1);
            }
        }
    }
}

// ---------------- kernel 5: down projection  y[tok] += (H@W2 + b2) * w ----------------
__global__ __launch_bounds__(256, 1) void k_down(const float* __restrict__ W2,
                                                 const float* __restrict__ b2,
                                                 float* __restrict__ y) {
    const int e = blockIdx.z;
    const int cnt = g_counts[e];
    const int mt = blockIdx.y;
    if (mt * BM >= cnt) return;
    const int nt = blockIdx.x;
    const int seg = g_offsets[e];
    const int tid = threadIdx.x;

    __shared__ unsigned As[2][BM][KPAD];
    __shared__ unsigned Bs[2][BN2][KPAD];

    const int rA = tid >> 2;
    const int cA = (tid & 3) * 4;
    int rowA0 = seg + mt * BM + rA; if (rowA0 > ATOT - 1) rowA0 = ATOT - 1;
    int rowA1 = rowA0 + 64;         if (rowA1 > ATOT - 1) rowA1 = ATOT - 1;
    const float* a0p = g_H + (size_t)rowA0 * INTER + cA;
    const float* a1p = g_H + (size_t)rowA1 * INTER + cA;

    const int nB = (tid & 31) * 4;
    const int kB = tid >> 5;  // 0..7
    const float* bp = W2 + (size_t)e * INTER * DIM + (size_t)kB * DIM + (size_t)nt * BN2 + nB;

    const int warp = tid >> 5, lane = tid & 31;
    const int wm = warp & 3, wn = warp >> 2;
    const int g = lane >> 2, tg = lane & 3;

    float acc[2][8][4];
#pragma unroll
    for (int i = 0; i < 2; i++)
#pragma unroll
        for (int j = 0; j < 8; j++)
#pragma unroll
            for (int q = 0; q < 4; q++) acc[i][j][q] = 0.f;

    float4 ra0, ra1, rb0, rb1;
    ra0 = *reinterpret_cast<const float4*>(a0p);
    ra1 = *reinterpret_cast<const float4*>(a1p);
    rb0 = *reinterpret_cast<const float4*>(bp);
    rb1 = *reinterpret_cast<const float4*>(bp + (size_t)8 * DIM);
    sts_a(As[0], rA, cA, ra0, ra1);
    sts_bT(Bs[0], nB, kB, rb0);
    sts_bT(Bs[0], nB, kB + 8, rb1);
    __syncthreads();

    const int NKT = INTER / BK;  // 128
#pragma unroll 1
    for (int kt = 0; kt < NKT; kt++) {
        const int nxt = kt + 1;
        if (nxt < NKT) {
            ra0 = *reinterpret_cast<const float4*>(a0p + nxt * BK);
            ra1 = *reinterpret_cast<const float4*>(a1p + nxt * BK);
            rb0 = *reinterpret_cast<const float4*>(bp + (size_t)nxt * BK * DIM);
            rb1 = *reinterpret_cast<const float4*>(bp + (size_t)(nxt * BK + 8) * DIM);
        }
        const int buf = kt & 1;
#pragma unroll
        for (int ks = 0; ks < 2; ks++) {
            unsigned af[2][4];
#pragma unroll
            for (int mi = 0; mi < 2; mi++) {
                const int mr = wm * 32 + mi * 16;
                af[mi][0] = As[buf][mr + g][ks * 8 + tg];
                af[mi][1] = As[buf][mr + g + 8][ks * 8 + tg];
                af[mi][2] = As[buf][mr + g][ks * 8 + tg + 4];
                af[mi][3] = As[buf][mr + g + 8][ks * 8 + tg + 4];
            }
            unsigned bf[8][2];
#pragma unroll
            for (int ni = 0; ni < 8; ni++) {
                const int nc = wn * 64 + ni * 8 + g;
                bf[ni][0] = Bs[buf][nc][ks * 8 + tg];
                bf[ni][1] = Bs[buf][nc][ks * 8 + tg + 4];
            }
#pragma unroll
            for (int mi = 0; mi < 2; mi++)
#pragma unroll
                for (int ni = 0; ni < 8; ni++)
                    mma8(acc[mi][ni], af[mi][0], af[mi][1], af[mi][2], af[mi][3], bf[ni][0], bf[ni][1]);
        }
        if (nxt < NKT) {
            const int b2f = nxt & 1;
            sts_a(As[b2f], rA, cA, ra0, ra1);
            sts_bT(Bs[b2f], nB, kB, rb0);
            sts_bT(Bs[b2f], nB, kB + 8, rb1);
        }
        __syncthreads();
    }

    // epilogue: weighted atomic accumulation into y
#pragma unroll
    for (int mi = 0; mi < 2; mi++) {
        const int rloc0 = mt * BM + wm * 32 + mi * 16 + g;
        const int rloc1 = rloc0 + 8;
        int t0 = 0, t1 = 0;
        float w0 = 0.f, w1 = 0.f;
        if (rloc0 < cnt) { t0 = g_tok[seg + rloc0]; w0 = g_w[seg + rloc0]; }
        if (rloc1 < cnt) { t1 = g_tok[seg + rloc1]; w1 = g_w[seg + rloc1]; }
#pragma unroll
        for (int ni = 0; ni < 8; ni++) {
            const int col = nt * BN2 + wn * 64 + ni * 8 + 2 * tg;
            const float bbx = b2[e * DIM + col], bby = b2[e * DIM + col + 1];
            if (rloc0 < cnt) {
                atomicAdd(&y[(size_t)t0 * DIM + col],     (acc[mi][ni][0] + bbx) * w0);
                atomicAdd(&y[(size_t)t0 * DIM + col + 1], (acc[mi][ni][1] + bby) * w0);
            }
            if (rloc1 < cnt) {
                atomicAdd(&y[(size_t)t1 * DIM + col],     (acc[mi][ni][2] + bbx) * w1);
                atomicAdd(&y[(size_t)t1 * DIM + col + 1], (acc[mi][ni][3] + bby) * w1);
            }
        }
    }
}

// ---------------- launch ----------------
extern "C" void kernel_launch(void* const* d_in, const int* in_sizes, int n_in,
                              void* d_out, int out_size) {
    const float* x  = (const float*)d_in[0];
    const float* Wg = (const float*)d_in[1];
    const float* bg = (const float*)d_in[2];
    const float* W1 = (const float*)d_in[3];
    const float* b1 = (const float*)d_in[4];
    const float* W2 = (const float*)d_in[5];
    const float* b2 = (const float*)d_in[6];
    const float* W3 = (const float*)d_in[7];
    const float* b3 = (const float*)d_in[8];
    float* y = (float*)d_out;

    const int n4 = T_TOK * DIM / 4;
    k_zero<<<(n4 + 255) / 256, 256>>>(y);
    k_gate<<<T_TOK / 8, 256>>>(x, Wg, bg);
    k_prefix<<<1, 1>>>();
    k_scatter<<<(T_TOK + 255) / 256, 256>>>();

    dim3 gglu(INTER / BN, (T_TOK + BM - 1) / BM, NEXP);   // 32 x 64 x 16
    k_glu<<<gglu, 256>>>(x, W1, b1, W3, b3);

    dim3 gdown(DIM / BN2, (T_TOK + BM - 1) / BM, NEXP);   // 8 x 64 x 16
    k_down<<<gdown, 256>>>(W2, b2, y);
}

// round 2
// speedup vs baseline: 3.1220x; 3.1220x over previous
#include <cuda_runtime.h>
#include <cuda_fp16.h>

#define T_TOK 8192
#define DIM 1024
#define NEXP 16
#define TOPK 2
#define INTER 2048
#define ATOT (T_TOK * TOPK)

#define BM 128
#define BN 64      // glu: cols per weight matrix
#define BN2 128    // down: cols
#define BK 32
#define BKA 40     // A smem row pitch (halves), +16B pad for conflict-free LDSM
#define BNP 72     // glu B smem row pitch (halves)
#define BNP2 136   // down B smem row pitch (halves)

// ---------------- scratch (static device globals; no allocation) ----------------
__device__ __half g_xh[(size_t)T_TOK * DIM];    // x in fp16 (16 MB)
__device__ __half g_Hh[(size_t)ATOT * INTER];   // H in fp16 (67 MB)
__device__ int   g_ti[ATOT];
__device__ float g_tw[ATOT];
__device__ int   g_counts[NEXP];
__device__ int   g_offsets[NEXP];
__device__ int   g_cursor[NEXP];
__device__ int   g_tok[ATOT];
__device__ float g_w[ATOT];

// ---------------- helpers ----------------
__device__ __forceinline__ unsigned su32(const void* p) {
    return (unsigned)__cvta_generic_to_shared(p);
}
__device__ __forceinline__ void ldsm4(unsigned addr, unsigned* r) {
    asm volatile("ldmatrix.sync.aligned.m8n8.x4.shared.b16 {%0,%1,%2,%3}, [%4];"
                 : "=r"(r[0]), "=r"(r[1]), "=r"(r[2]), "=r"(r[3]) : "r"(addr));
}
__device__ __forceinline__ void ldsm4t(unsigned addr, unsigned* r) {
    asm volatile("ldmatrix.sync.aligned.m8n8.x4.trans.shared.b16 {%0,%1,%2,%3}, [%4];"
                 : "=r"(r[0]), "=r"(r[1]), "=r"(r[2]), "=r"(r[3]) : "r"(addr));
}
__device__ __forceinline__ void mma16(float* c, const unsigned* a, unsigned b0, unsigned b1) {
    asm volatile(
        "mma.sync.aligned.m16n8k16.row.col.f32.f16.f16.f32 "
        "{%0,%1,%2,%3},{%4,%5,%6,%7},{%8,%9},{%0,%1,%2,%3};"
        : "+f"(c[0]), "+f"(c[1]), "+f"(c[2]), "+f"(c[3])
        : "r"(a[0]), "r"(a[1]), "r"(a[2]), "r"(a[3]), "r"(b0), "r"(b1));
}
__device__ __forceinline__ void cpa16(unsigned saddr, const void* g) {
    asm volatile("cp.async.cg.shared.global [%0], [%1], 16;" :: "r"(saddr), "l"(g));
}
#define CP_COMMIT asm volatile("cp.async.commit_group;")
#define CP_WAIT0  asm volatile("cp.async.wait_group 0;")

__device__ __forceinline__ uint4 pack8(float4 a, float4 b) {
    uint4 u;
    __half2 h;
    h = __floats2half2_rn(a.x, a.y); u.x = *(unsigned*)&h;
    h = __floats2half2_rn(a.z, a.w); u.y = *(unsigned*)&h;
    h = __floats2half2_rn(b.x, b.y); u.z = *(unsigned*)&h;
    h = __floats2half2_rn(b.z, b.w); u.w = *(unsigned*)&h;
    return u;
}
__device__ __forceinline__ float silu_f(float v) {
    return v * (1.f / (1.f + __expf(-v)));
}

// ---------------- kernel: convert x to fp16 ----------------
__global__ void k_xconv(const float* __restrict__ x) {
    const int i = blockIdx.x * blockDim.x + threadIdx.x;
    const int n4 = T_TOK * DIM / 4;
    if (i < n4) {
        float4 v = reinterpret_cast<const float4*>(x)[i];
        __half2 a = __floats2half2_rn(v.x, v.y);
        __half2 b = __floats2half2_rn(v.z, v.w);
        reinterpret_cast<__half2*>(g_xh)[2 * i]     = a;
        reinterpret_cast<__half2*>(g_xh)[2 * i + 1] = b;
    }
}

// ---------------- kernel: zero output + counters ----------------
__global__ void k_zero(float* __restrict__ y) {
    int i = blockIdx.x * blockDim.x + threadIdx.x;
    const int n4 = T_TOK * DIM / 4;
    if (i < n4) reinterpret_cast<float4*>(y)[i] = make_float4(0.f, 0.f, 0.f, 0.f);
    if (i < NEXP) { g_counts[i] = 0; g_cursor[i] = 0; }
}

// ---------------- kernel: gate (warp per token, fp32 exact) ----------------
__global__ __launch_bounds__(256) void k_gate(const float* __restrict__ x,
                                              const float* __restrict__ Wg,
                                              const float* __restrict__ bg) {
    const int warp = threadIdx.x >> 5, lane = threadIdx.x & 31;
    const int t = blockIdx.x * 8 + warp;
    if (t >= T_TOK) return;

    float acc[NEXP];
#pragma unroll
    for (int e = 0; e < NEXP; e++) acc[e] = 0.f;

    const float* xr = x + (size_t)t * DIM;
#pragma unroll 4
    for (int i = 0; i < DIM / 32; i++) {
        const int d = i * 32 + lane;
        const float xv = xr[d];
        const float4* wr = reinterpret_cast<const float4*>(Wg + (size_t)d * NEXP);
        float4 w0 = wr[0], w1 = wr[1], w2 = wr[2], w3 = wr[3];
        acc[0] += xv * w0.x;  acc[1] += xv * w0.y;  acc[2] += xv * w0.z;  acc[3] += xv * w0.w;
        acc[4] += xv * w1.x;  acc[5] += xv * w1.y;  acc[6] += xv * w1.z;  acc[7] += xv * w1.w;
        acc[8] += xv * w2.x;  acc[9] += xv * w2.y;  acc[10] += xv * w2.z; acc[11] += xv * w2.w;
        acc[12] += xv * w3.x; acc[13] += xv * w3.y; acc[14] += xv * w3.z; acc[15] += xv * w3.w;
    }
#pragma unroll
    for (int e = 0; e < NEXP; e++) {
        float v = acc[e];
#pragma unroll
        for (int o = 16; o > 0; o >>= 1) v += __shfl_xor_sync(0xffffffffu, v, o);
        acc[e] = v + bg[e];
    }
    float mx = acc[0];
#pragma unroll
    for (int e = 1; e < NEXP; e++) mx = fmaxf(mx, acc[e]);
    float p[NEXP];
#pragma unroll
    for (int e = 0; e < NEXP; e++) p[e] = __expf(acc[e] - mx);

    int i0, i1; float p0, p1;
    if (p[0] >= p[1]) { i0 = 0; p0 = p[0]; i1 = 1; p1 = p[1]; }
    else              { i0 = 1; p0 = p[1]; i1 = 0; p1 = p[0]; }
#pragma unroll
    for (int e = 2; e < NEXP; e++) {
        if (p[e] > p0)      { i1 = i0; p1 = p0; i0 = e; p0 = p[e]; }
        else if (p[e] > p1) { i1 = e; p1 = p[e]; }
    }
    if (lane == 0) {
        const float ws = p0 + p1;
        g_ti[2 * t] = i0;     g_tw[2 * t] = p0 / ws;
        g_ti[2 * t + 1] = i1; g_tw[2 * t + 1] = p1 / ws;
        atomicAdd(&g_counts[i0], 1);
        atomicAdd(&g_counts[i1], 1);
    }
}

// ---------------- prefix + scatter ----------------
__global__ void k_prefix() {
    int s = 0;
    for (int e = 0; e < NEXP; e++) { g_offsets[e] = s; s += g_counts[e]; }
}
__global__ void k_scatter() {
    const int t = blockIdx.x * blockDim.x + threadIdx.x;
    if (t >= T_TOK) return;
#pragma unroll
    for (int k = 0; k < TOPK; k++) {
        const int e = g_ti[2 * t + k];
        const int slot = atomicAdd(&g_cursor[e], 1);
        const int pos = g_offsets[e] + slot;
        g_tok[pos] = t;
        g_w[pos] = g_tw[2 * t + k];
    }
}

// ---------------- kernel: fused GLU GEMM (fp16 mma) ----------------
// grid: (mtile, ntile, expert) — mtile fastest for L2 weight reuse
__global__ __launch_bounds__(256, 2) void k_glu(const float* __restrict__ W1, const float* __restrict__ b1,
                                                const float* __restrict__ W3, const float* __restrict__ b3) {
    const int e = blockIdx.z;
    const int cnt = g_counts[e];
    const int mt = blockIdx.x;
    if (mt * BM >= cnt) return;
    const int nt = blockIdx.y;
    const int seg = g_offsets[e];
    const int tid = threadIdx.x;

    __shared__ __half As[2][BM][BKA];
    __shared__ __half B1s[2][BK][BNP];
    __shared__ __half B3s[2][BK][BNP];

    // A (cp.async): thread handles rows rA and rA+64, 16B segment sA
    const int rA = tid >> 2;
    const int sA = (tid & 3) * 8;  // halves
    const int r0 = mt * BM + rA, r1 = r0 + 64;
    const int tok0 = (r0 < cnt) ? g_tok[seg + r0] : 0;
    const int tok1 = (r1 < cnt) ? g_tok[seg + r1] : 0;
    const __half* a0g = g_xh + (size_t)tok0 * DIM + sA;
    const __half* a1g = g_xh + (size_t)tok1 * DIM + sA;

    // B (LDG fp32 -> cvt -> STS fp16): thread owns row kB, 8 cols at nB
    const int kB = tid >> 3;          // 0..31
    const int nB = (tid & 7) * 8;     // 0..56
    const float* w1p = W1 + (size_t)e * DIM * INTER + (size_t)kB * INTER + nt * BN + nB;
    const float* w3p = W3 + (size_t)e * DIM * INTER + (size_t)kB * INTER + nt * BN + nB;

    const int warp = tid >> 5, lane = tid & 31;
    const int wm = warp & 3, wn = warp >> 2;   // 4m x 2n
    const int lrow = lane & 15, lseg = (lane >> 4) * 8;
    const int g = lane >> 2, tg = lane & 3;

    float acc1[2][4][4], acc3[2][4][4];
#pragma unroll
    for (int i = 0; i < 2; i++)
#pragma unroll
        for (int j = 0; j < 4; j++)
#pragma unroll
            for (int q = 0; q < 4; q++) { acc1[i][j][q] = 0.f; acc3[i][j][q] = 0.f; }

    // prologue: stage buffer 0
    cpa16(su32(&As[0][rA][sA]), a0g);
    cpa16(su32(&As[0][rA + 64][sA]), a1g);
    CP_COMMIT;
    {
        float4 f10 = *(const float4*)(w1p), f11 = *(const float4*)(w1p + 4);
        float4 f30 = *(const float4*)(w3p), f31 = *(const float4*)(w3p + 4);
        *(uint4*)&B1s[0][kB][nB] = pack8(f10, f11);
        *(uint4*)&B3s[0][kB][nB] = pack8(f30, f31);
    }
    CP_WAIT0;
    __syncthreads();

    const int NKT = DIM / BK;  // 32
    float4 f10, f11, f30, f31;
#pragma unroll 1
    for (int kt = 0; kt < NKT; kt++) {
        const int nxt = kt + 1;
        const int buf = kt & 1, nb = nxt & 1;
        if (nxt < NKT) {
            cpa16(su32(&As[nb][rA][sA]), a0g + nxt * BK);
            cpa16(su32(&As[nb][rA + 64][sA]), a1g + nxt * BK);
            CP_COMMIT;
            const float* p1 = w1p + (size_t)nxt * BK * INTER;
            const float* p3 = w3p + (size_t)nxt * BK * INTER;
            f10 = *(const float4*)(p1); f11 = *(const float4*)(p1 + 4);
            f30 = *(const float4*)(p3); f31 = *(const float4*)(p3 + 4);
        }
#pragma unroll
        for (int ks = 0; ks < 2; ks++) {
            unsigned af[2][4];
#pragma unroll
            for (int mi = 0; mi < 2; mi++)
                ldsm4(su32(&As[buf][wm * 32 + mi * 16 + lrow][ks * 16 + lseg]), af[mi]);
            unsigned bf1[2][4], bf3[2][4];
#pragma unroll
            for (int j = 0; j < 2; j++) {
                ldsm4t(su32(&B1s[buf][ks * 16 + lrow][wn * 32 + j * 16 + lseg]), bf1[j]);
                ldsm4t(su32(&B3s[buf][ks * 16 + lrow][wn * 32 + j * 16 + lseg]), bf3[j]);
            }
#pragma unroll
            for (int mi = 0; mi < 2; mi++)
#pragma unroll
                for (int j = 0; j < 2; j++) {
                    mma16(acc1[mi][2 * j],     af[mi], bf1[j][0], bf1[j][1]);
                    mma16(acc1[mi][2 * j + 1], af[mi], bf1[j][2], bf1[j][3]);
                    mma16(acc3[mi][2 * j],     af[mi], bf3[j][0], bf3[j][1]);
                    mma16(acc3[mi][2 * j + 1], af[mi], bf3[j][2], bf3[j][3]);
                }
        }
        if (nxt < NKT) {
            *(uint4*)&B1s[nb][kB][nB] = pack8(f10, f11);
            *(uint4*)&B3s[nb][kB][nB] = pack8(f30, f31);
            CP_WAIT0;
        }
        __syncthreads();
    }

    // epilogue: h = silu(v1+b1)*(v3+b3), store fp16
#pragma unroll
    for (int mi = 0; mi < 2; mi++) {
        const int rl0 = mt * BM + wm * 32 + mi * 16 + g;
        const int rl1 = rl0 + 8;
#pragma unroll
        for (int ni = 0; ni < 4; ni++) {
            const int col = nt * BN + wn * 32 + ni * 8 + 2 * tg;
            const float bb1x = b1[e * INTER + col], bb1y = b1[e * INTER + col + 1];
            const float bb3x = b3[e * INTER + col], bb3y = b3[e * INTER + col + 1];
            if (rl0 < cnt) {
                const float h0 = silu_f(acc1[mi][ni][0] + bb1x) * (acc3[mi][ni][0] + bb3x);
                const float h1 = silu_f(acc1[mi][ni][1] + bb1y) * (acc3[mi][ni][1] + bb3y);
                *reinterpret_cast<__half2*>(&g_Hh[(size_t)(seg + rl0) * INTER + col]) = __floats2half2_rn(h0, h1);
            }
            if (rl1 < cnt) {
                const float h0 = silu_f(acc1[mi][ni][2] + bb1x) * (acc3[mi][ni][2] + bb3x);
                const float h1 = silu_f(acc1[mi][ni][3] + bb1y) * (acc3[mi][ni][3] + bb3y);
                *reinterpret_cast<__half2*>(&g_Hh[(size_t)(seg + rl1) * INTER + col]) = __floats2half2_rn(h0, h1);
            }
        }
    }
}

// ---------------- kernel: down projection (fp16 mma) ----------------
__global__ __launch_bounds__(256, 2) void k_down(const float* __restrict__ W2,
                                                 const float* __restrict__ b2,
                                                 float* __restrict__ y) {
    const int e = blockIdx.z;
    const int cnt = g_counts[e];
    const int mt = blockIdx.x;
    if (mt * BM >= cnt) return;
    const int nt = blockIdx.y;
    const int seg = g_offsets[e];
    const int tid = threadIdx.x;

    __shared__ __half As[2][BM][BKA];
    __shared__ __half Bs[2][BK][BNP2];

    const int rA = tid >> 2;
    const int sA = (tid & 3) * 8;
    int ar0 = seg + mt * BM + rA; if (ar0 > ATOT - 1) ar0 = ATOT - 1;
    int ar1 = ar0 + 64;           if (ar1 > ATOT - 1) ar1 = ATOT - 1;
    const __half* a0g = g_Hh + (size_t)ar0 * INTER + sA;
    const __half* a1g = g_Hh + (size_t)ar1 * INTER + sA;

    const int kB = tid >> 3;       // 0..31
    const int nB = (tid & 7) * 16; // 0..112
    const float* w2p = W2 + (size_t)e * INTER * DIM + (size_t)kB * DIM + nt * BN2 + nB;

    const int warp = tid >> 5, lane = tid & 31;
    const int wm = warp & 3, wn = warp >> 2;   // 4m x 2n (64 cols per warp)
    const int lrow = lane & 15, lseg = (lane >> 4) * 8;
    const int g = lane >> 2, tg = lane & 3;

    float acc[2][8][4];
#pragma unroll
    for (int i = 0; i < 2; i++)
#pragma unroll
        for (int j = 0; j < 8; j++)
#pragma unroll
            for (int q = 0; q < 4; q++) acc[i][j][q] = 0.f;

    cpa16(su32(&As[0][rA][sA]), a0g);
    cpa16(su32(&As[0][rA + 64][sA]), a1g);
    CP_COMMIT;
    {
        float4 f0 = *(const float4*)(w2p),     f1 = *(const float4*)(w2p + 4);
        float4 f2 = *(const float4*)(w2p + 8), f3 = *(const float4*)(w2p + 12);
        *(uint4*)&Bs[0][kB][nB]     = pack8(f0, f1);
        *(uint4*)&Bs[0][kB][nB + 8] = pack8(f2, f3);
    }
    CP_WAIT0;
    __syncthreads();

    const int NKT = INTER / BK;  // 64
    float4 f0, f1, f2, f3;
#pragma unroll 1
    for (int kt = 0; kt < NKT; kt++) {
        const int nxt = kt + 1;
        const int buf = kt & 1, nb = nxt & 1;
        if (nxt < NKT) {
            cpa16(su32(&As[nb][rA][sA]), a0g + nxt * BK);
            cpa16(su32(&As[nb][rA + 64][sA]), a1g + nxt * BK);
            CP_COMMIT;
            const float* p = w2p + (size_t)nxt * BK * DIM;
            f0 = *(const float4*)(p);     f1 = *(const float4*)(p + 4);
            f2 = *(const float4*)(p + 8); f3 = *(const float4*)(p + 12);
        }
#pragma unroll
        for (int ks = 0; ks < 2; ks++) {
            unsigned af[2][4];
#pragma unroll
            for (int mi = 0; mi < 2; mi++)
                ldsm4(su32(&As[buf][wm * 32 + mi * 16 + lrow][ks * 16 + lseg]), af[mi]);
            unsigned bf[4][4];
#pragma unroll
            for (int j = 0; j < 4; j++)
                ldsm4t(su32(&Bs[buf][ks * 16 + lrow][wn * 64 + j * 16 + lseg]), bf[j]);
#pragma unroll
            for (int mi = 0; mi < 2; mi++)
#pragma unroll
                for (int j = 0; j < 4; j++) {
                    mma16(acc[mi][2 * j],     af[mi], bf[j][0], bf[j][1]);
                    mma16(acc[mi][2 * j + 1], af[mi], bf[j][2], bf[j][3]);
                }
        }
        if (nxt < NKT) {
            *(uint4*)&Bs[nb][kB][nB]     = pack8(f0, f1);
            *(uint4*)&Bs[nb][kB][nB + 8] = pack8(f2, f3);
            CP_WAIT0;
        }
        __syncthreads();
    }

    // epilogue: weighted atomic accumulation into y
#pragma unroll
    for (int mi = 0; mi < 2; mi++) {
        const int rl0 = mt * BM + wm * 32 + mi * 16 + g;
        const int rl1 = rl0 + 8;
        int t0 = 0, t1 = 0;
        float w0 = 0.f, w1 = 0.f;
        if (rl0 < cnt) { t0 = g_tok[seg + rl0]; w0 = g_w[seg + rl0]; }
        if (rl1 < cnt) { t1 = g_tok[seg + rl1]; w1 = g_w[seg + rl1]; }
#pragma unroll
        for (int ni = 0; ni < 8; ni++) {
            const int col = nt * BN2 + wn * 64 + ni * 8 + 2 * tg;
            const float bbx = b2[e * DIM + col], bby = b2[e * DIM + col + 1];
            if (rl0 < cnt) {
                atomicAdd(&y[(size_t)t0 * DIM + col],     (acc[mi][ni][0] + bbx) * w0);
                atomicAdd(&y[(size_t)t0 * DIM + col + 1], (acc[mi][ni][1] + bby) * w0);
            }
            if (rl1 < cnt) {
                atomicAdd(&y[(size_t)t1 * DIM + col],     (acc[mi][ni][2] + bbx) * w1);
                atomicAdd(&y[(size_t)t1 * DIM + col + 1], (acc[mi][ni][3] + bby) * w1);
            }
        }
    }
}

// ---------------- launch ----------------
extern "C" void kernel_launch(void* const* d_in, const int* in_sizes, int n_in,
                              void* d_out, int out_size) {
    const float* x  = (const float*)d_in[0];
    const float* Wg = (const float*)d_in[1];
    const float* bg = (const float*)d_in[2];
    const float* W1 = (const float*)d_in[3];
    const float* b1 = (const float*)d_in[4];
    const float* W2 = (const float*)d_in[5];
    const float* b2 = (const float*)d_in[6];
    const float* W3 = (const float*)d_in[7];
    const float* b3 = (const float*)d_in[8];
    float* y = (float*)d_out;

    const int n4 = T_TOK * DIM / 4;
    k_xconv<<<(n4 + 255) / 256, 256>>>(x);
    k_zero<<<(n4 + 255) / 256, 256>>>(y);
    k_gate<<<T_TOK / 8, 256>>>(x, Wg, bg);
    k_prefix<<<1, 1>>>();
    k_scatter<<<(T_TOK + 255) / 256, 256>>>();

    dim3 gglu(T_TOK / BM, INTER / BN, NEXP);   // (64 mt, 32 nt, 16 e) — mt fastest
    k_glu<<<gglu, 256>>>(W1, b1, W3, b3);

    dim3 gdown(T_TOK / BM, DIM / BN2, NEXP);   // (64 mt, 8 nt, 16 e)
    k_down<<<gdown, 256>>>(W2, b2, y);
}

// round 4
// speedup vs baseline: 3.5230x; 1.1285x over previous
#include <cuda_runtime.h>
#include <cuda_fp16.h>
#include <cstdint>

#define T_TOK 8192
#define DIM 1024
#define NEXP 16
#define TOPK 2
#define INTER 2048
#define ATOT (T_TOK * TOPK)

#define BM 128
#define BNG 128        // glu: cols per weight matrix (W1 and W3 => 256 B-cols total)
#define BND 256        // down: output cols per CTA
#define BK 32
#define STAGES 4
#define APITCH 40      // halves; 80B rows -> conflict-free ldsm
#define BPITCH 264     // halves; 528B rows -> conflict-free ldsm
#define A_ST_HALVES (BM * APITCH)
#define B_ST_HALVES (BK * BPITCH)
#define DSMEM_SZ (STAGES * (A_ST_HALVES + B_ST_HALVES) * 2)   // ~108.5 KB

// ---------------- scratch (static device globals; no allocation) ----------------
__device__ __half g_xh[(size_t)T_TOK * DIM];          // 16 MB
__device__ __half g_Hh[(size_t)ATOT * INTER];         // 67 MB
__device__ __half g_W1h[(size_t)NEXP * DIM * INTER];  // 67 MB  [E][K][N]
__device__ __half g_W3h[(size_t)NEXP * DIM * INTER];  // 67 MB
__device__ __half g_W2h[(size_t)NEXP * INTER * DIM];  // 67 MB
__device__ float  g_Yp[(size_t)ATOT * DIM];           // 67 MB
__device__ int   g_ti[ATOT];
__device__ float g_tw[ATOT];
__device__ int   g_counts[NEXP];
__device__ int   g_offsets[NEXP];
__device__ int   g_cursor[NEXP];
__device__ int   g_tok[ATOT];
__device__ float g_w[ATOT];
__device__ int   g_pos[ATOT];

// ---------------- helpers ----------------
__device__ __forceinline__ uint32_t su32(const void* p) {
    return (uint32_t)__cvta_generic_to_shared(p);
}
__device__ __forceinline__ void ldsm4(uint32_t addr, unsigned* r) {
    asm volatile("ldmatrix.sync.aligned.m8n8.x4.shared.b16 {%0,%1,%2,%3}, [%4];"
                 : "=r"(r[0]), "=r"(r[1]), "=r"(r[2]), "=r"(r[3]) : "r"(addr));
}
__device__ __forceinline__ void ldsm4t(uint32_t addr, unsigned* r) {
    asm volatile("ldmatrix.sync.aligned.m8n8.x4.trans.shared.b16 {%0,%1,%2,%3}, [%4];"
                 : "=r"(r[0]), "=r"(r[1]), "=r"(r[2]), "=r"(r[3]) : "r"(addr));
}
__device__ __forceinline__ void mma16(float* c, const unsigned* a, unsigned b0, unsigned b1) {
    asm volatile(
        "mma.sync.aligned.m16n8k16.row.col.f32.f16.f16.f32 "
        "{%0,%1,%2,%3},{%4,%5,%6,%7},{%8,%9},{%0,%1,%2,%3};"
        : "+f"(c[0]), "+f"(c[1]), "+f"(c[2]), "+f"(c[3])
        : "r"(a[0]), "r"(a[1]), "r"(a[2]), "r"(a[3]), "r"(b0), "r"(b1));
}
__device__ __forceinline__ void cpa16(uint32_t saddr, const void* g) {
    asm volatile("cp.async.cg.shared.global [%0], [%1], 16;" :: "r"(saddr), "l"(g));
}
#define CP_COMMIT asm volatile("cp.async.commit_group;" ::: "memory")
#define CP_WAIT2  asm volatile("cp.async.wait_group 2;" ::: "memory")

__device__ __forceinline__ uint4 pack8(float4 a, float4 b) {
    uint4 u;
    __half2 h;
    h = __floats2half2_rn(a.x, a.y); u.x = *(unsigned*)&h;
    h = __floats2half2_rn(a.z, a.w); u.y = *(unsigned*)&h;
    h = __floats2half2_rn(b.x, b.y); u.z = *(unsigned*)&h;
    h = __floats2half2_rn(b.z, b.w); u.w = *(unsigned*)&h;
    return u;
}
__device__ __forceinline__ float silu_f(float v) {
    return v * (1.f / (1.f + __expf(-v)));
}

// ---------------- small kernels ----------------
__global__ void k_wconv(const float* __restrict__ src, __half* __restrict__ dst, size_t n8) {
    const size_t i = (size_t)blockIdx.x * blockDim.x + threadIdx.x;
    if (i >= n8) return;
    const float4 a = reinterpret_cast<const float4*>(src)[2 * i];
    const float4 b = reinterpret_cast<const float4*>(src)[2 * i + 1];
    reinterpret_cast<uint4*>(dst)[i] = pack8(a, b);
}

__global__ void k_xconv(const float* __restrict__ x) {
    const int i = blockIdx.x * blockDim.x + threadIdx.x;
    const int n4 = T_TOK * DIM / 4;
    if (i < n4) {
        float4 v = reinterpret_cast<const float4*>(x)[i];
        reinterpret_cast<__half2*>(g_xh)[2 * i]     = __floats2half2_rn(v.x, v.y);
        reinterpret_cast<__half2*>(g_xh)[2 * i + 1] = __floats2half2_rn(v.z, v.w);
    }
    if (i < NEXP) { g_counts[i] = 0; g_cursor[i] = 0; }
}

__global__ __launch_bounds__(256) void k_gate(const float* __restrict__ x,
                                              const float* __restrict__ Wg,
                                              const float* __restrict__ bg) {
    const int warp = threadIdx.x >> 5, lane = threadIdx.x & 31;
    const int t = blockIdx.x * 8 + warp;
    if (t >= T_TOK) return;
    float acc[NEXP];
#pragma unroll
    for (int e = 0; e < NEXP; e++) acc[e] = 0.f;
    const float* xr = x + (size_t)t * DIM;
#pragma unroll 4
    for (int i = 0; i < DIM / 32; i++) {
        const int d = i * 32 + lane;
        const float xv = xr[d];
        const float4* wr = reinterpret_cast<const float4*>(Wg + (size_t)d * NEXP);
        float4 w0 = wr[0], w1 = wr[1], w2 = wr[2], w3 = wr[3];
        acc[0] += xv * w0.x;  acc[1] += xv * w0.y;  acc[2] += xv * w0.z;  acc[3] += xv * w0.w;
        acc[4] += xv * w1.x;  acc[5] += xv * w1.y;  acc[6] += xv * w1.z;  acc[7] += xv * w1.w;
        acc[8] += xv * w2.x;  acc[9] += xv * w2.y;  acc[10] += xv * w2.z; acc[11] += xv * w2.w;
        acc[12] += xv * w3.x; acc[13] += xv * w3.y; acc[14] += xv * w3.z; acc[15] += xv * w3.w;
    }
#pragma unroll
    for (int e = 0; e < NEXP; e++) {
        float v = acc[e];
#pragma unroll
        for (int o = 16; o > 0; o >>= 1) v += __shfl_xor_sync(0xffffffffu, v, o);
        acc[e] = v + bg[e];
    }
    float mx = acc[0];
#pragma unroll
    for (int e = 1; e < NEXP; e++) mx = fmaxf(mx, acc[e]);
    float p[NEXP];
#pragma unroll
    for (int e = 0; e < NEXP; e++) p[e] = __expf(acc[e] - mx);
    int i0, i1; float p0, p1;
    if (p[0] >= p[1]) { i0 = 0; p0 = p[0]; i1 = 1; p1 = p[1]; }
    else              { i0 = 1; p0 = p[1]; i1 = 0; p1 = p[0]; }
#pragma unroll
    for (int e = 2; e < NEXP; e++) {
        if (p[e] > p0)      { i1 = i0; p1 = p0; i0 = e; p0 = p[e]; }
        else if (p[e] > p1) { i1 = e; p1 = p[e]; }
    }
    if (lane == 0) {
        const float ws = p0 + p1;
        g_ti[2 * t] = i0;     g_tw[2 * t] = p0 / ws;
        g_ti[2 * t + 1] = i1; g_tw[2 * t + 1] = p1 / ws;
        atomicAdd(&g_counts[i0], 1);
        atomicAdd(&g_counts[i1], 1);
    }
}

__global__ void k_prefix() {
    int s = 0;
    for (int e = 0; e < NEXP; e++) { g_offsets[e] = s; s += g_counts[e]; }
}
__global__ void k_scatter() {
    const int t = blockIdx.x * blockDim.x + threadIdx.x;
    if (t >= T_TOK) return;
#pragma unroll
    for (int k = 0; k < TOPK; k++) {
        const int e = g_ti[2 * t + k];
        const int slot = atomicAdd(&g_cursor[e], 1);
        const int pos = g_offsets[e] + slot;
        g_tok[pos] = t;
        g_w[pos] = g_tw[2 * t + k];
        g_pos[2 * t + k] = pos;
    }
}

// ---------------- fused GLU GEMM: H = silu(xW1+b1)*(xW3+b3) ----------------
// 512 threads, tile 128 x (128+128), BK=32, 4-stage cp.async pipeline
__global__ __launch_bounds__(512, 1) void k_glu(const float* __restrict__ b1,
                                                const float* __restrict__ b3) {
    const int e = blockIdx.z;
    const int cnt = g_counts[e];
    const int mt = blockIdx.x;
    if (mt * BM >= cnt) return;
    const int nt = blockIdx.y;
    const int seg = g_offsets[e];
    const int tid = threadIdx.x;
    const int wid = tid >> 5, lane = tid & 31;

    extern __shared__ __half sm[];
    __half* As = sm;                              // [STAGES][BM][APITCH]
    __half* Bs = sm + STAGES * A_ST_HALVES;       // [STAGES][BK][BPITCH]

    // A loader: one 16B seg per thread per stage
    const int aRow = tid >> 2;
    const int aSeg = (tid & 3) * 8;
    const int grow = mt * BM + aRow;
    const int prow = seg + ((grow < cnt) ? grow : (cnt - 1));
    const __half* aptr = g_xh + (size_t)g_tok[prow] * DIM + aSeg;

    // B loader: 2 segs per thread per stage (W1 col block + W3 col block)
    const int bK = tid >> 4;           // 0..31
    const int bSeg = (tid & 15) * 8;   // 0..120 halves
    const __half* w1p = g_W1h + (size_t)e * DIM * INTER + (size_t)bK * INTER + nt * BNG + bSeg;
    const __half* w3p = g_W3h + (size_t)e * DIM * INTER + (size_t)bK * INTER + nt * BNG + bSeg;

    const int wm = wid & 3, wn = wid >> 2;   // 4m x 4n
    const int lrow = lane & 15, lseg = (lane >> 4) * 8;
    const int g = lane >> 2, tg = lane & 3;

    float acc1[2][4][4], acc3[2][4][4];
#pragma unroll
    for (int i = 0; i < 2; i++)
#pragma unroll
        for (int j = 0; j < 4; j++)
#pragma unroll
            for (int q = 0; q < 4; q++) { acc1[i][j][q] = 0.f; acc3[i][j][q] = 0.f; }

#pragma unroll
    for (int c = 0; c < STAGES - 1; c++) {
        cpa16(su32(&As[(size_t)c * A_ST_HALVES + aRow * APITCH + aSeg]), aptr + c * BK);
        cpa16(su32(&Bs[(size_t)c * B_ST_HALVES + bK * BPITCH + bSeg]), w1p + (size_t)c * BK * INTER);
        cpa16(su32(&Bs[(size_t)c * B_ST_HALVES + bK * BPITCH + 128 + bSeg]), w3p + (size_t)c * BK * INTER);
        CP_COMMIT;
    }

    const int NKT = DIM / BK;  // 32
#pragma unroll 1
    for (int j = 0; j < NKT; j++) {
        CP_WAIT2;
        __syncthreads();
        const int st = j & (STAGES - 1);
        const __half* Ab = As + (size_t)st * A_ST_HALVES;
        const __half* Bb = Bs + (size_t)st * B_ST_HALVES;
#pragma unroll
        for (int ks = 0; ks < 2; ks++) {
            unsigned af[2][4];
#pragma unroll
            for (int mi = 0; mi < 2; mi++)
                ldsm4(su32(&Ab[(wm * 32 + mi * 16 + lrow) * APITCH + ks * 16 + lseg]), af[mi]);
#pragma unroll
            for (int nh = 0; nh < 2; nh++) {
                unsigned bf[4];
                ldsm4t(su32(&Bb[(ks * 16 + lrow) * BPITCH + wn * 32 + nh * 16 + lseg]), bf);
#pragma unroll
                for (int mi = 0; mi < 2; mi++) {
                    mma16(acc1[mi][2 * nh],     af[mi], bf[0], bf[1]);
                    mma16(acc1[mi][2 * nh + 1], af[mi], bf[2], bf[3]);
                }
            }
#pragma unroll
            for (int nh = 0; nh < 2; nh++) {
                unsigned bf[4];
                ldsm4t(su32(&Bb[(ks * 16 + lrow) * BPITCH + 128 + wn * 32 + nh * 16 + lseg]), bf);
#pragma unroll
                for (int mi = 0; mi < 2; mi++) {
                    mma16(acc3[mi][2 * nh],     af[mi], bf[0], bf[1]);
                    mma16(acc3[mi][2 * nh + 1], af[mi], bf[2], bf[3]);
                }
            }
        }
        const int nc = j + STAGES - 1;
        if (nc < NKT) {
            const int ns = nc & (STAGES - 1);
            cpa16(su32(&As[(size_t)ns * A_ST_HALVES + aRow * APITCH + aSeg]), aptr + nc * BK);
            cpa16(su32(&Bs[(size_t)ns * B_ST_HALVES + bK * BPITCH + bSeg]), w1p + (size_t)nc * BK * INTER);
            cpa16(su32(&Bs[(size_t)ns * B_ST_HALVES + bK * BPITCH + 128 + bSeg]), w3p + (size_t)nc * BK * INTER);
        }
        CP_COMMIT;
    }

    // epilogue: h = silu(v1+b1)*(v3+b3) -> fp16
#pragma unroll
    for (int mi = 0; mi < 2; mi++) {
        const int rl0 = mt * BM + wm * 32 + mi * 16 + g;
        const int rl1 = rl0 + 8;
#pragma unroll
        for (int ni = 0; ni < 4; ni++) {
            const int col = nt * BNG + wn * 32 + ni * 8 + 2 * tg;
            const float bb1x = b1[e * INTER + col], bb1y = b1[e * INTER + col + 1];
            const float bb3x = b3[e * INTER + col], bb3y = b3[e * INTER + col + 1];
            if (rl0 < cnt) {
                const float h0 = silu_f(acc1[mi][ni][0] + bb1x) * (acc3[mi][ni][0] + bb3x);
                const float h1 = silu_f(acc1[mi][ni][1] + bb1y) * (acc3[mi][ni][1] + bb3y);
                *reinterpret_cast<__half2*>(&g_Hh[(size_t)(seg + rl0) * INTER + col]) = __floats2half2_rn(h0, h1);
            }
            if (rl1 < cnt) {
                const float h0 = silu_f(acc1[mi][ni][2] + bb1x) * (acc3[mi][ni][2] + bb3x);
                const float h1 = silu_f(acc1[mi][ni][3] + bb1y) * (acc3[mi][ni][3] + bb3y);
                *reinterpret_cast<__half2*>(&g_Hh[(size_t)(seg + rl1) * INTER + col]) = __floats2half2_rn(h0, h1);
            }
        }
    }
}

// ---------------- down GEMM: Yp = (H@W2 + b2) * w ----------------
// 512 threads, tile 128 x 256, BK=32, 4-stage pipeline
__global__ __launch_bounds__(512, 1) void k_down(const float* __restrict__ b2) {
    const int e = blockIdx.z;
    const int cnt = g_counts[e];
    const int mt = blockIdx.x;
    if (mt * BM >= cnt) return;
    const int nt = blockIdx.y;
    const int seg = g_offsets[e];
    const int tid = threadIdx.x;
    const int wid = tid >> 5, lane = tid & 31;

    extern __shared__ __half sm[];
    __half* As = sm;
    __half* Bs = sm + STAGES * A_ST_HALVES;

    const int aRow = tid >> 2;
    const int aSeg = (tid & 3) * 8;
    int ar = seg + mt * BM + aRow;
    if (ar > ATOT - 1) ar = ATOT - 1;
    const __half* aptr = g_Hh + (size_t)ar * INTER + aSeg;

    const int bK = tid >> 4;
    const int bSeg = (tid & 15) * 8;
    const __half* w2p = g_W2h + (size_t)e * INTER * DIM + (size_t)bK * DIM + nt * BND + bSeg;

    const int wm = wid & 3, wn = wid >> 2;   // 4m x 4n, warp tile 32x64
    const int lrow = lane & 15, lseg = (lane >> 4) * 8;
    const int g = lane >> 2, tg = lane & 3;

    float acc[2][8][4];
#pragma unroll
    for (int i = 0; i < 2; i++)
#pragma unroll
        for (int j = 0; j < 8; j++)
#pragma unroll
            for (int q = 0; q < 4; q++) acc[i][j][q] = 0.f;

#pragma unroll
    for (int c = 0; c < STAGES - 1; c++) {
        cpa16(su32(&As[(size_t)c * A_ST_HALVES + aRow * APITCH + aSeg]), aptr + c * BK);
        cpa16(su32(&Bs[(size_t)c * B_ST_HALVES + bK * BPITCH + bSeg]), w2p + (size_t)c * BK * DIM);
        cpa16(su32(&Bs[(size_t)c * B_ST_HALVES + bK * BPITCH + 128 + bSeg]), w2p + 128 + (size_t)c * BK * DIM);
        CP_COMMIT;
    }

    const int NKT = INTER / BK;  // 64
#pragma unroll 1
    for (int j = 0; j < NKT; j++) {
        CP_WAIT2;
        __syncthreads();
        const int st = j & (STAGES - 1);
        const __half* Ab = As + (size_t)st * A_ST_HALVES;
        const __half* Bb = Bs + (size_t)st * B_ST_HALVES;
#pragma unroll
        for (int ks = 0; ks < 2; ks++) {
            unsigned af[2][4];
#pragma unroll
            for (int mi = 0; mi < 2; mi++)
                ldsm4(su32(&Ab[(wm * 32 + mi * 16 + lrow) * APITCH + ks * 16 + lseg]), af[mi]);
#pragma unroll
            for (int nh = 0; nh < 4; nh++) {
                unsigned bf[4];
                ldsm4t(su32(&Bb[(ks * 16 + lrow) * BPITCH + wn * 64 + nh * 16 + lseg]), bf);
#pragma unroll
                for (int mi = 0; mi < 2; mi++) {
                    mma16(acc[mi][2 * nh],     af[mi], bf[0], bf[1]);
                    mma16(acc[mi][2 * nh + 1], af[mi], bf[2], bf[3]);
                }
            }
        }
        const int nc = j + STAGES - 1;
        if (nc < NKT) {
            const int ns = nc & (STAGES - 1);
            cpa16(su32(&As[(size_t)ns * A_ST_HALVES + aRow * APITCH + aSeg]), aptr + nc * BK);
            cpa16(su32(&Bs[(size_t)ns * B_ST_HALVES + bK * BPITCH + bSeg]), w2p + (size_t)nc * BK * DIM);
            cpa16(su32(&Bs[(size_t)ns * B_ST_HALVES + bK * BPITCH + 128 + bSeg]), w2p + 128 + (size_t)nc * BK * DIM);
        }
        CP_COMMIT;
    }

    // epilogue: positional weighted write (no atomics)
#pragma unroll
    for (int mi = 0; mi < 2; mi++) {
        const int rl0 = mt * BM + wm * 32 + mi * 16 + g;
        const int rl1 = rl0 + 8;
        const int p0 = seg + rl0, p1 = seg + rl1;
        const float w0 = (rl0 < cnt) ? g_w[p0] : 0.f;
        const float w1 = (rl1 < cnt) ? g_w[p1] : 0.f;
#pragma unroll
        for (int ni = 0; ni < 8; ni++) {
            const int col = nt * BND + wn * 64 + ni * 8 + 2 * tg;
            const float bbx = b2[e * DIM + col], bby = b2[e * DIM + col + 1];
            if (rl0 < cnt)
                *reinterpret_cast<float2*>(&g_Yp[(size_t)p0 * DIM + col]) =
                    make_float2((acc[mi][ni][0] + bbx) * w0, (acc[mi][ni][1] + bby) * w0);
            if (rl1 < cnt)
                *reinterpret_cast<float2*>(&g_Yp[(size_t)p1 * DIM + col]) =
                    make_float2((acc[mi][ni][2] + bbx) * w1, (acc[mi][ni][3] + bby) * w1);
        }
    }
}

// ---------------- combine: y[t] = Yp[p0] + Yp[p1] ----------------
__global__ void k_combine(float* __restrict__ y) {
    const int idx = blockIdx.x * blockDim.x + threadIdx.x;
    const int n4 = T_TOK * DIM / 4;
    if (idx >= n4) return;
    const int t = idx / (DIM / 4);
    const int c4 = idx % (DIM / 4);
    const int p0 = g_pos[2 * t], p1 = g_pos[2 * t + 1];
    const float4 a = reinterpret_cast<const float4*>(g_Yp)[(size_t)p0 * (DIM / 4) + c4];
    const float4 b = reinterpret_cast<const float4*>(g_Yp)[(size_t)p1 * (DIM / 4) + c4];
    reinterpret_cast<float4*>(y)[idx] = make_float4(a.x + b.x, a.y + b.y, a.z + b.z, a.w + b.w);
}

// ---------------- launch ----------------
extern "C" void kernel_launch(void* const* d_in, const int* in_sizes, int n_in,
                              void* d_out, int out_size) {
    const float* x  = (const float*)d_in[0];
    const float* Wg = (const float*)d_in[1];
    const float* bg = (const float*)d_in[2];
    const float* W1 = (const float*)d_in[3];
    const float* b1 = (const float*)d_in[4];
    const float* W2 = (const float*)d_in[5];
    const float* b2 = (const float*)d_in[6];
    const float* W3 = (const float*)d_in[7];
    const float* b3 = (const float*)d_in[8];
    float* y = (float*)d_out;

    cudaFuncSetAttribute(k_glu,  cudaFuncAttributeMaxDynamicSharedMemorySize, DSMEM_SZ);
    cudaFuncSetAttribute(k_down, cudaFuncAttributeMaxDynamicSharedMemorySize, DSMEM_SZ);

    // weight conversion fp32 -> fp16 (same layout)
    const size_t wn8 = (size_t)NEXP * DIM * INTER / 8;
    __half* w1h; cudaGetSymbolAddress((void**)&w1h, g_W1h);
    __half* w3h; cudaGetSymbolAddress((void**)&w3h, g_W3h);
    __half* w2h; cudaGetSymbolAddress((void**)&w2h, g_W2h);
    k_wconv<<<(unsigned)((wn8 + 255) / 256), 256>>>(W1, w1h, wn8);
    k_wconv<<<(unsigned)((wn8 + 255) / 256), 256>>>(W3, w3h, wn8);
    k_wconv<<<(unsigned)((wn8 + 255) / 256), 256>>>(W2, w2h, wn8);

    const int n4 = T_TOK * DIM / 4;
    k_xconv<<<(n4 + 255) / 256, 256>>>(x);
    k_gate<<<T_TOK / 8, 256>>>(x, Wg, bg);
    k_prefix<<<1, 1>>>();
    k_scatter<<<(T_TOK + 255) / 256, 256>>>();

    dim3 gglu(T_TOK / BM, INTER / BNG, NEXP);    // (64, 16, 16), mt fastest
    k_glu<<<gglu, 512, DSMEM_SZ>>>(b1, b3);

    dim3 gdown(T_TOK / BM, DIM / BND, NEXP);     // (64, 4, 16)
    k_down<<<gdown, 512, DSMEM_SZ>>>(b2);

    k_combine<<<(n4 + 255) / 256, 256>>>(y);
}